// round 2
// baseline (speedup 1.0000x reference)
#include <cuda_runtime.h>

#define BD 128
#define SD 512
#define ED 192
#define NROWS (BD*SD)   // 65536

// ---------------- scratch (__device__ globals; no runtime alloc) ----------------
__device__ __align__(16) float g_qkv[(size_t)2*3*BD*3*SD*16]; // [br*3+{q,k,v}][b][h][s][16]
__device__ __align__(16) float g_conv[(size_t)NROWS*96];
__device__ __align__(16) float g_attn[(size_t)2*NROWS*48];    // [br][row][48]
__device__ __align__(16) float g_x1[(size_t)NROWS*ED];
__device__ __align__(16) float g_xn2[(size_t)NROWS*ED];
__device__ __align__(16) float g_tt[(size_t)NROWS*384];

// ---------------- packed fp32x2 helpers (exact fp32, sm_100+) ----------------
__device__ __forceinline__ unsigned long long pk(float lo, float hi) {
    unsigned long long r;
    asm("mov.b64 %0, {%1, %2};" : "=l"(r) : "f"(lo), "f"(hi));
    return r;
}
__device__ __forceinline__ void upk(unsigned long long v, float& lo, float& hi) {
    asm("mov.b64 {%0, %1}, %2;" : "=f"(lo), "=f"(hi) : "l"(v));
}
__device__ __forceinline__ unsigned long long fma2(unsigned long long a, unsigned long long b, unsigned long long c) {
    unsigned long long d;
    asm("fma.rn.f32x2 %0, %1, %2, %3;" : "=l"(d) : "l"(a), "l"(b), "l"(c));
    return d;
}
__device__ __forceinline__ unsigned long long mul2(unsigned long long a, unsigned long long b) {
    unsigned long long d;
    asm("mul.rn.f32x2 %0, %1, %2;" : "=l"(d) : "l"(a), "l"(b));
    return d;
}

// ============================================================================
// Kernel A: LN1 + depthwise conv (k=15, ch = row%4) + QKV for both branches.
// 16 rows/block, 256 threads.
// ============================================================================
__global__ void __launch_bounds__(256) kA(
    const float* __restrict__ x,
    const float* __restrict__ ln1_g, const float* __restrict__ ln1_b,
    const float* __restrict__ wqA, const float* __restrict__ bqA,
    const float* __restrict__ wqG, const float* __restrict__ bqG,
    const float* __restrict__ convw)
{
    extern __shared__ float sm[];
    float* xn = sm;                  // 16*193
    float* wA = xn + 16*193;         // 144*49
    float* wG = wA + 144*49;         // 144*49
    float* bA = wG + 144*49;         // 144
    float* bG = bA + 144;            // 144
    float* cw = bG + 144;            // 4*16
    float* lg = cw + 64;             // 192
    float* lb = lg + 192;            // 192
    const int t = threadIdx.x;

    for (int i = t; i < 144*48; i += 256) {
        int o = i / 48, j = i - o*48;
        wA[o*49+j] = wqA[i];
        wG[o*49+j] = wqG[i];
    }
    for (int i = t; i < 144; i += 256) { bA[i] = bqA[i]; bG[i] = bqG[i]; }
    if (t < 60) cw[(t/15)*16 + (t%15)] = convw[t];
    for (int i = t; i < 192; i += 256) { lg[i] = ln1_g[i]; lb[i] = ln1_b[i]; }

    const int row0 = blockIdx.x * 16;
    for (int i = t; i < 16*192; i += 256) {
        int r = i / 192, c = i - r*192;
        xn[r*193+c] = x[(size_t)(row0+r)*192 + c];
    }
    __syncthreads();

    // ---- LayerNorm: 16 threads/row, width-16 shfl reduction ----
    {
        const int r = t >> 4, part = t & 15;
        float* xr = xn + r*193 + part*12;
        float s0 = 0.f, s1 = 0.f;
        #pragma unroll
        for (int j = 0; j < 12; j++) { float v = xr[j]; s0 += v; s1 += v*v; }
        #pragma unroll
        for (int d = 8; d; d >>= 1) {
            s0 += __shfl_xor_sync(0xffffffffu, s0, d, 16);
            s1 += __shfl_xor_sync(0xffffffffu, s1, d, 16);
        }
        const float mean = s0 * (1.f/192.f);
        const float var  = s1 * (1.f/192.f) - mean*mean;
        const float rinv = rsqrtf(var + 1e-6f);
        const float* lgp = lg + part*12;
        const float* lbp = lb + part*12;
        #pragma unroll
        for (int j = 0; j < 12; j++) xr[j] = (xr[j]-mean)*rinv*lgp[j] + lbp[j];
    }
    __syncthreads();

    // ---- depthwise conv over cols [48,144) ----
    #pragma unroll
    for (int q = 0; q < 6; q++) {
        int o = t + q*256;                 // 0..1535 = 16 rows * 96 cols
        int r = o / 96, c = o - r*96;
        const float* w  = cw + ((row0 + r) & 3) * 16;
        const float* xr = xn + r*193 + 48;
        float acc = 0.f;
        #pragma unroll
        for (int k = 0; k < 15; k++) {
            int idx = c + k - 7;
            if (idx >= 0 && idx < 96) acc += xr[idx] * w[k];
        }
        g_conv[(size_t)(row0+r)*96 + c] = acc;
    }

    // ---- QKV: thread = (row, 9-output group), both branches ----
    {
        const int r = t >> 4, og = t & 15;
        const int grow = row0 + r;
        const int b = grow >> 9, s = grow & 511;
        #pragma unroll
        for (int br = 0; br < 2; br++) {
            const float* ws = br ? wG : wA;
            const float* bs = br ? bG : bA;
            const float* xr = xn + r*193 + br*96;
            float acc[9];
            #pragma unroll
            for (int i = 0; i < 9; i++) acc[i] = bs[og*9+i];
            const float* wrow = ws + og*9*49;
            #pragma unroll 4
            for (int j = 0; j < 48; j++) {
                float xv = xr[j];
                #pragma unroll
                for (int i = 0; i < 9; i++) acc[i] += xv * wrow[i*49 + j];
            }
            #pragma unroll
            for (int i = 0; i < 9; i++) {
                int o = og*9 + i;
                int which = o / 48;
                int rem = o - which*48;
                int h = rem >> 4, d = rem & 15;
                size_t idx = ((((size_t)(br*3 + which)*BD + b)*3 + h)*SD + s)*16 + d;
                g_qkv[idx] = acc[i];
            }
        }
    }
}

// ============================================================================
// Kernel B: streaming-softmax attention. Grid (4, 6, 128), 128 thr, 1 q/thread.
// ============================================================================
__global__ void __launch_bounds__(128) kB()
{
    __shared__ __align__(16) float ks[64*16];
    __shared__ __align__(16) float vs[64*16];
    const int t  = threadIdx.x;
    const int b  = blockIdx.z;
    const int br = blockIdx.y / 3, h = blockIdx.y % 3;
    const int q0 = blockIdx.x * 128;

    const size_t qbase = (((size_t)(br*3+0)*BD + b)*3 + h)*(size_t)SD*16;
    const size_t kbase = (((size_t)(br*3+1)*BD + b)*3 + h)*(size_t)SD*16;
    const size_t vbase = (((size_t)(br*3+2)*BD + b)*3 + h)*(size_t)SD*16;

    unsigned long long q2[8];
    {
        const float4* q4 = (const float4*)(g_qkv + qbase + (size_t)(q0 + t)*16);
        #pragma unroll
        for (int i = 0; i < 4; i++) {
            float4 v = q4[i];
            q2[2*i]   = pk(v.x*0.25f, v.y*0.25f);   // fold 1/sqrt(16) into q
            q2[2*i+1] = pk(v.z*0.25f, v.w*0.25f);
        }
    }
    unsigned long long o2[8];
    #pragma unroll
    for (int i = 0; i < 8; i++) o2[i] = 0ULL;
    float m = -1e30f, l = 0.f;

    for (int kt = 0; kt < 8; kt++) {
        __syncthreads();
        const float4* kp = (const float4*)(g_qkv + kbase + (size_t)kt*64*16);
        const float4* vp = (const float4*)(g_qkv + vbase + (size_t)kt*64*16);
        #pragma unroll
        for (int i = 0; i < 2; i++) {
            ((float4*)ks)[t + i*128] = kp[t + i*128];
            ((float4*)vs)[t + i*128] = vp[t + i*128];
        }
        __syncthreads();

        #pragma unroll 2
        for (int j0 = 0; j0 < 64; j0 += 8) {
            float sc[8];
            #pragma unroll
            for (int jj = 0; jj < 8; jj++) {
                const unsigned long long* kr = (const unsigned long long*)(ks + (j0+jj)*16);
                unsigned long long a0 = mul2(q2[0], kr[0]);
                unsigned long long a1 = mul2(q2[1], kr[1]);
                a0 = fma2(q2[2], kr[2], a0); a1 = fma2(q2[3], kr[3], a1);
                a0 = fma2(q2[4], kr[4], a0); a1 = fma2(q2[5], kr[5], a1);
                a0 = fma2(q2[6], kr[6], a0); a1 = fma2(q2[7], kr[7], a1);
                float x0,x1,y0,y1; upk(a0,x0,x1); upk(a1,y0,y1);
                sc[jj] = (x0+x1) + (y0+y1);
            }
            float cm = sc[0];
            #pragma unroll
            for (int jj = 1; jj < 8; jj++) cm = fmaxf(cm, sc[jj]);
            float mnew  = fmaxf(m, cm);
            float scale = __expf(m - mnew);
            float p[8]; float psum = 0.f;
            #pragma unroll
            for (int jj = 0; jj < 8; jj++) { p[jj] = __expf(sc[jj] - mnew); psum += p[jj]; }
            l = l*scale + psum;
            unsigned long long s2 = pk(scale, scale);
            #pragma unroll
            for (int i = 0; i < 8; i++) o2[i] = mul2(o2[i], s2);
            #pragma unroll
            for (int jj = 0; jj < 8; jj++) {
                unsigned long long p2 = pk(p[jj], p[jj]);
                const unsigned long long* vr = (const unsigned long long*)(vs + (j0+jj)*16);
                #pragma unroll
                for (int i = 0; i < 8; i++) o2[i] = fma2(p2, vr[i], o2[i]);
            }
            m = mnew;
        }
    }
    const float il = 1.f / l;
    float ov[16];
    #pragma unroll
    for (int i = 0; i < 8; i++) { float lo, hi; upk(o2[i], lo, hi); ov[2*i]=lo*il; ov[2*i+1]=hi*il; }
    float4* o4 = (float4*)(g_attn + ((size_t)br*NROWS + (size_t)b*SD + (q0+t))*48 + h*16);
    #pragma unroll
    for (int i = 0; i < 4; i++) o4[i] = make_float4(ov[4*i], ov[4*i+1], ov[4*i+2], ov[4*i+3]);
}

// ============================================================================
// Kernel C: O-proj (both branches) + concat + residual + LN2.
// 32 rows/block, 256 threads.
// ============================================================================
__global__ void __launch_bounds__(256) kC(
    const float* __restrict__ x,
    const float* __restrict__ woA, const float* __restrict__ boA,
    const float* __restrict__ woG, const float* __restrict__ boG,
    const float* __restrict__ ln2_g, const float* __restrict__ ln2_b)
{
    extern __shared__ float sm[];
    float* wo  = sm;             // 2*48*49
    float* bo  = wo + 2*48*49;   // 96
    float* aa  = bo + 96;        // 2*32*49
    float* x1s = aa + 2*32*49;   // 32*193
    float* lg  = x1s + 32*193;   // 192
    float* lb  = lg + 192;       // 192
    const int t = threadIdx.x;

    for (int i = t; i < 48*48; i += 256) {
        int o = i/48, j = i - o*48;
        wo[o*49+j]         = woA[i];
        wo[48*49 + o*49+j] = woG[i];
    }
    if (t < 96) bo[t] = (t < 48) ? boA[t] : boG[t-48];
    for (int i = t; i < 192; i += 256) { lg[i] = ln2_g[i]; lb[i] = ln2_b[i]; }

    const int row0 = blockIdx.x * 32;
    for (int i = t; i < 2*32*48; i += 256) {
        int br  = i / (32*48);
        int rem = i - br*32*48;
        int r = rem / 48, j = rem - r*48;
        aa[br*32*49 + r*49 + j] = g_attn[((size_t)br*NROWS + row0 + r)*48 + j];
    }
    __syncthreads();

    // ---- O-projection: thread = (row, branch, 12-col group) ----
    {
        const int r = t >> 3, og = t & 7;
        const int br = og >> 2;
        const int ob = (og & 3) * 12;
        const float* ar = aa + br*32*49 + r*49;
        const float* wr = wo + br*48*49 + ob*49;
        float acc[12];
        #pragma unroll
        for (int i = 0; i < 12; i++) acc[i] = bo[br*48 + ob + i];
        #pragma unroll 4
        for (int j = 0; j < 48; j++) {
            float av = ar[j];
            #pragma unroll
            for (int i = 0; i < 12; i++) acc[i] += av * wr[i*49 + j];
        }
        const int cbase = br ? 144 + ob : ob;
        #pragma unroll
        for (int i = 0; i < 12; i++) x1s[r*193 + cbase + i] = acc[i];
    }
    __syncthreads();

    // ---- insert conv slice + residual ----
    for (int i = t; i < 32*192; i += 256) {
        int r = i / 192, c = i - r*192;
        size_t grow = (size_t)row0 + r;
        float v = (c >= 48 && c < 144) ? g_conv[grow*96 + (c-48)] : x1s[r*193+c];
        v += x[grow*192 + c];
        x1s[r*193+c] = v;
    }
    __syncthreads();

    // ---- LN2: 8 threads/row; emits x1 and LN2(x1) ----
    {
        const int r = t >> 3, part = t & 7;
        float* xr = x1s + r*193 + part*24;
        float s0 = 0.f, s1 = 0.f;
        #pragma unroll
        for (int j = 0; j < 24; j++) { float v = xr[j]; s0 += v; s1 += v*v; }
        #pragma unroll
        for (int d = 4; d; d >>= 1) {
            s0 += __shfl_xor_sync(0xffffffffu, s0, d, 8);
            s1 += __shfl_xor_sync(0xffffffffu, s1, d, 8);
        }
        const float mean = s0*(1.f/192.f);
        const float var  = s1*(1.f/192.f) - mean*mean;
        const float rinv = rsqrtf(var + 1e-6f);
        size_t grow = (size_t)row0 + r;
        const float* lgp = lg + part*24;
        const float* lbp = lb + part*24;
        float* px1 = g_x1  + grow*192 + part*24;
        float* pxn = g_xn2 + grow*192 + part*24;
        #pragma unroll
        for (int j = 0; j < 24; j++) {
            float v = xr[j];
            px1[j] = v;
            pxn[j] = (v-mean)*rinv*lgp[j] + lbp[j];
        }
    }
}

// ============================================================================
// GEMM: C[M,N] = [resid +] relu(A[M,K] @ W[N,K]^T + bias)
// BM=128, BN=64, BK=64, 256 threads, 8x4 thread tile, f32x2 outer product.
// mode 0: A=g_xn2 -> g_tt.  mode 1: A=g_tt -> outp (+resid g_x1).
// ============================================================================
__global__ void __launch_bounds__(256) kGEMM(
    const float* __restrict__ W, const float* __restrict__ bias,
    float* __restrict__ outp, int K, int N, int mode)
{
    const float* __restrict__ A     = mode ? g_tt : g_xn2;
    const float* __restrict__ resid = mode ? g_x1 : nullptr;
    float* __restrict__ C           = mode ? outp : g_tt;

    extern __shared__ float sm[];
    float* As = sm;            // [kk 0..63][r 0..127], stride 132 (k-major)
    float* Ws = As + 64*132;   // [kk 0..63][n 0..63], stride 66

    const int t  = threadIdx.x;
    const int m0 = blockIdx.x * 128;
    const int n0 = blockIdx.y * 64;
    const int rg = t >> 4, cg = t & 15;
    const int lr = t >> 4, lc = t & 15;    // A loader
    const int wn = t >> 2, wk = t & 3;     // W loader

    unsigned long long c2[8][2];
    #pragma unroll
    for (int i = 0; i < 8; i++) { c2[i][0]=0ULL; c2[i][1]=0ULL; }

    for (int k0 = 0; k0 < K; k0 += 64) {
        __syncthreads();
        #pragma unroll
        for (int p = 0; p < 8; p++) {
            int r = p*16 + lr;
            float4 v = *(const float4*)(A + (size_t)(m0 + r)*K + k0 + lc*4);
            As[(lc*4+0)*132 + r] = v.x;
            As[(lc*4+1)*132 + r] = v.y;
            As[(lc*4+2)*132 + r] = v.z;
            As[(lc*4+3)*132 + r] = v.w;
        }
        #pragma unroll
        for (int j4 = 0; j4 < 4; j4++) {
            int kk = wk*16 + j4*4;
            float4 v = *(const float4*)(W + (size_t)(n0 + wn)*K + k0 + kk);
            Ws[(kk+0)*66 + wn] = v.x;
            Ws[(kk+1)*66 + wn] = v.y;
            Ws[(kk+2)*66 + wn] = v.z;
            Ws[(kk+3)*66 + wn] = v.w;
        }
        __syncthreads();

        #pragma unroll 4
        for (int kk = 0; kk < 64; kk++) {
            const unsigned long long* wr = (const unsigned long long*)(Ws + kk*66 + cg*4);
            unsigned long long b0 = wr[0], b1 = wr[1];
            float4 va = *(const float4*)(As + kk*132 + rg*8);
            float4 vb = *(const float4*)(As + kk*132 + rg*8 + 4);
            unsigned long long a2;
            a2 = pk(va.x, va.x); c2[0][0]=fma2(a2,b0,c2[0][0]); c2[0][1]=fma2(a2,b1,c2[0][1]);
            a2 = pk(va.y, va.y); c2[1][0]=fma2(a2,b0,c2[1][0]); c2[1][1]=fma2(a2,b1,c2[1][1]);
            a2 = pk(va.z, va.z); c2[2][0]=fma2(a2,b0,c2[2][0]); c2[2][1]=fma2(a2,b1,c2[2][1]);
            a2 = pk(va.w, va.w); c2[3][0]=fma2(a2,b0,c2[3][0]); c2[3][1]=fma2(a2,b1,c2[3][1]);
            a2 = pk(vb.x, vb.x); c2[4][0]=fma2(a2,b0,c2[4][0]); c2[4][1]=fma2(a2,b1,c2[4][1]);
            a2 = pk(vb.y, vb.y); c2[5][0]=fma2(a2,b0,c2[5][0]); c2[5][1]=fma2(a2,b1,c2[5][1]);
            a2 = pk(vb.z, vb.z); c2[6][0]=fma2(a2,b0,c2[6][0]); c2[6][1]=fma2(a2,b1,c2[6][1]);
            a2 = pk(vb.w, vb.w); c2[7][0]=fma2(a2,b0,c2[7][0]); c2[7][1]=fma2(a2,b1,c2[7][1]);
        }
    }

    const float bv0 = bias[n0+cg*4+0], bv1 = bias[n0+cg*4+1];
    const float bv2 = bias[n0+cg*4+2], bv3 = bias[n0+cg*4+3];
    #pragma unroll
    for (int i = 0; i < 8; i++) {
        float v0,v1,v2,v3;
        upk(c2[i][0], v0, v1); upk(c2[i][1], v2, v3);
        v0 = fmaxf(v0 + bv0, 0.f);
        v1 = fmaxf(v1 + bv1, 0.f);
        v2 = fmaxf(v2 + bv2, 0.f);
        v3 = fmaxf(v3 + bv3, 0.f);
        size_t row = (size_t)m0 + rg*8 + i;
        if (resid) {
            const float4 rv = *(const float4*)(resid + row*N + n0 + cg*4);
            v0 += rv.x; v1 += rv.y; v2 += rv.z; v3 += rv.w;
        }
        *(float4*)(C + row*N + n0 + cg*4) = make_float4(v0,v1,v2,v3);
    }
}

// ============================================================================
extern "C" void kernel_launch(void* const* d_in, const int* in_sizes, int n_in,
                              void* d_out, int out_size)
{
    (void)in_sizes; (void)n_in; (void)out_size;
    const float* x         = (const float*)d_in[0];
    const float* ln1_g     = (const float*)d_in[1];
    const float* ln1_b     = (const float*)d_in[2];
    const float* acc_wqkv  = (const float*)d_in[3];
    const float* acc_bqkv  = (const float*)d_in[4];
    const float* acc_wo    = (const float*)d_in[5];
    const float* acc_bo    = (const float*)d_in[6];
    const float* gyro_wqkv = (const float*)d_in[7];
    const float* gyro_bqkv = (const float*)d_in[8];
    const float* gyro_wo   = (const float*)d_in[9];
    const float* gyro_bo   = (const float*)d_in[10];
    const float* conv_w    = (const float*)d_in[11];
    const float* ln2_g     = (const float*)d_in[12];
    const float* ln2_b     = (const float*)d_in[13];
    const float* w1        = (const float*)d_in[14];
    const float* b1        = (const float*)d_in[15];
    const float* w2        = (const float*)d_in[16];
    const float* b2        = (const float*)d_in[17];
    float* out = (float*)d_out;

    const int SM_A = (16*193 + 2*144*49 + 2*144 + 64 + 2*192) * 4;
    const int SM_C = (2*48*49 + 96 + 2*32*49 + 32*193 + 2*192) * 4;
    const int SM_G = (64*132 + 64*66) * 4;
    cudaFuncSetAttribute(kA,    cudaFuncAttributeMaxDynamicSharedMemorySize, SM_A);
    cudaFuncSetAttribute(kC,    cudaFuncAttributeMaxDynamicSharedMemorySize, SM_C);
    cudaFuncSetAttribute(kGEMM, cudaFuncAttributeMaxDynamicSharedMemorySize, SM_G);

    kA<<<NROWS/16, 256, SM_A>>>(x, ln1_g, ln1_b, acc_wqkv, acc_bqkv,
                                gyro_wqkv, gyro_bqkv, conv_w);
    kB<<<dim3(4, 6, BD), 128>>>();
    kC<<<NROWS/32, 256, SM_C>>>(x, acc_wo, acc_bo, gyro_wo, gyro_bo, ln2_g, ln2_b);
    kGEMM<<<dim3(NROWS/128, 384/64), 256, SM_G>>>(w1, b1, nullptr, 192, 384, 0);
    kGEMM<<<dim3(NROWS/128, 192/64), 256, SM_G>>>(w2, b2, out,     384, 192, 1);
}